// round 17
// baseline (speedup 1.0000x reference)
#include <cuda_runtime.h>
#include <cuda_fp16.h>
#include <math.h>
#include <stdint.h>

#define SEQ    2048
#define BATCH  2
#define DIM    1024
#define HEADS  16
#define DH     64
#define MROWS  (BATCH*SEQ)          // 4096
#define QKVCOL (3*DIM)              // 3072
#define QSCALE 0.1803368801111244f  // 0.125 * log2(e)

__device__ __half g_qkvh[MROWS * QKVCOL];   // fp16 qkv (Q pre-scaled by QSCALE)
__device__ __half g_attnh[MROWS * DIM];     // fp16 attention output
__device__ __half g_xh  [MROWS * DIM];
__device__ __half g_wqh [QKVCOL * DIM];
__device__ __half g_woh [DIM * DIM];

// ---------------------------------------------------------------------------
__device__ __forceinline__ uint32_t smem_u32(const void* p){
    return (uint32_t)__cvta_generic_to_shared(p);
}
__device__ __forceinline__ uint32_t pkh(float lo, float hi){
    __half2 h = __floats2half2_rn(lo, hi);
    return *reinterpret_cast<uint32_t*>(&h);
}
__device__ __forceinline__ void mma16(float* c, const uint32_t* a, const uint32_t* b){
    asm volatile("mma.sync.aligned.m16n8k16.row.col.f32.f16.f16.f32 "
        "{%0,%1,%2,%3}, {%4,%5,%6,%7}, {%8,%9}, {%0,%1,%2,%3};"
        : "+f"(c[0]),"+f"(c[1]),"+f"(c[2]),"+f"(c[3])
        : "r"(a[0]),"r"(a[1]),"r"(a[2]),"r"(a[3]),"r"(b[0]),"r"(b[1]));
}
__device__ __forceinline__ void ldsm4(uint32_t& r0, uint32_t& r1, uint32_t& r2, uint32_t& r3,
                                      uint32_t addr){
    asm volatile("ldmatrix.sync.aligned.m8n8.x4.shared.b16 {%0,%1,%2,%3}, [%4];"
        : "=r"(r0),"=r"(r1),"=r"(r2),"=r"(r3) : "r"(addr));
}
__device__ __forceinline__ void ldsm4t(uint32_t& r0, uint32_t& r1, uint32_t& r2, uint32_t& r3,
                                       uint32_t addr){
    asm volatile("ldmatrix.sync.aligned.m8n8.x4.trans.shared.b16 {%0,%1,%2,%3}, [%4];"
        : "=r"(r0),"=r"(r1),"=r"(r2),"=r"(r3) : "r"(addr));
}
#define STS16(addr, v) \
    asm volatile("st.shared.v4.b32 [%0], {%1,%2,%3,%4};" :: "r"(addr), \
                 "r"((v).x), "r"((v).y), "r"((v).z), "r"((v).w))

// ---------------------------------------------------------------------------
// fused fp32 -> fp16 convert for all three inputs
// ---------------------------------------------------------------------------
__global__ void cvt3(const float* __restrict__ a, __half* __restrict__ oa, int na8,
                     const float* __restrict__ b, __half* __restrict__ ob, int nb8,
                     const float* __restrict__ c, __half* __restrict__ oc, int nc8)
{
    int i = blockIdx.x * blockDim.x + threadIdx.x;
    const float* src; __half* dst; int j;
    if (i < na8)            { src = a; dst = oa; j = i; }
    else if (i < na8 + nb8) { src = b; dst = ob; j = i - na8; }
    else if (i < na8 + nb8 + nc8) { src = c; dst = oc; j = i - na8 - nb8; }
    else return;
    float4 v0 = ((const float4*)src)[2*j];
    float4 v1 = ((const float4*)src)[2*j+1];
    uint4 r;
    r.x = pkh(v0.x, v0.y); r.y = pkh(v0.z, v0.w);
    r.z = pkh(v1.x, v1.y); r.w = pkh(v1.z, v1.w);
    ((uint4*)dst)[j] = r;
}

// ---------------------------------------------------------------------------
// fp16 GEMM, BK=32, 3-stage smem pipeline (Round-16 version).
// ---------------------------------------------------------------------------
#define S112  112u
#define MBUF  (128*S112)
#define STGB  (2*MBUF)
#define G_SMEM (3*STGB)

__global__ void __launch_bounds__(256,2) gemm_h16(const __half* __restrict__ A,
                                                  const __half* __restrict__ B,
                                                  __half* __restrict__ Ch,
                                                  float* __restrict__ Cf,
                                                  int M, int N, int K, int scale_cols)
{
    extern __shared__ __align__(16) unsigned char smem[];
    const uint32_t sb = smem_u32(smem);

    const int tid  = threadIdx.x;
    const int lane = tid & 31, wid = tid >> 5;
    const int g = lane >> 2, t = lane & 3;
    const int wm = wid & 3, wn = wid >> 2;
    const int bm = blockIdx.y * 128, bn = blockIdx.x * 128;

    const uint32_t a_lo = (uint32_t)((lane & 15) * S112 + (lane >> 4) * 16);
    const uint32_t b_lo = (uint32_t)(((lane & 7) + ((lane >> 4) & 1) * 8) * S112 + ((lane >> 3) & 1) * 16);

    const int frow = tid >> 1;
    const __half* Ag = A + (size_t)(bm + frow) * K + (tid & 1) * 16;
    const __half* Bg = B + (size_t)(bn + frow) * K + (tid & 1) * 16;
    const uint32_t sA = sb + (uint32_t)(frow * S112 + (tid & 1) * 32);
    const uint32_t sB = sA + MBUF;

    float acc[2][8][4] = {};
    const int NC = K / 32;

    uint4 ra0 = ((const uint4*)Ag)[0], ra1 = ((const uint4*)Ag)[1];
    uint4 rb0 = ((const uint4*)Bg)[0], rb1 = ((const uint4*)Bg)[1];
    STS16(sA, ra0); STS16(sA + 16, ra1);
    STS16(sB, rb0); STS16(sB + 16, rb1);
    ra0 = ((const uint4*)(Ag + 32))[0]; ra1 = ((const uint4*)(Ag + 32))[1];
    rb0 = ((const uint4*)(Bg + 32))[0]; rb1 = ((const uint4*)(Bg + 32))[1];
    __syncthreads();

    int bufw = 1;
    for (int c = 0; c < NC; c++) {
        if (c + 1 < NC) {
            const uint32_t dA = sA + (uint32_t)bufw * STGB;
            const uint32_t dB = sB + (uint32_t)bufw * STGB;
            STS16(dA, ra0); STS16(dA + 16, ra1);
            STS16(dB, rb0); STS16(dB + 16, rb1);
        }
        if (c + 2 < NC) {
            const __half* Ag2 = Ag + (c + 2) * 32;
            const __half* Bg2 = Bg + (c + 2) * 32;
            ra0 = ((const uint4*)Ag2)[0]; ra1 = ((const uint4*)Ag2)[1];
            rb0 = ((const uint4*)Bg2)[0]; rb1 = ((const uint4*)Bg2)[1];
        }

        const int bufr = (bufw + 2) % 3;
        const uint32_t abase = sb + (uint32_t)bufr * STGB + (uint32_t)(wm * 32) * S112;
        const uint32_t bbase = abase + MBUF + (uint32_t)(wn * 64 - wm * 32) * S112;

        #pragma unroll
        for (int ks = 0; ks < 2; ks++) {
            uint32_t af[2][4], bf[8][2];
            #pragma unroll
            for (int ma = 0; ma < 2; ma++)
                ldsm4(af[ma][0], af[ma][1], af[ma][2], af[ma][3],
                      abase + (uint32_t)(ma * 16) * S112 + (uint32_t)(ks * 32) + a_lo);
            #pragma unroll
            for (int p = 0; p < 4; p++)
                ldsm4(bf[2*p][0], bf[2*p][1], bf[2*p+1][0], bf[2*p+1][1],
                      bbase + (uint32_t)(p * 16) * S112 + (uint32_t)(ks * 32) + b_lo);
            #pragma unroll
            for (int ma = 0; ma < 2; ma++)
                #pragma unroll
                for (int nb = 0; nb < 8; nb++)
                    mma16(acc[ma][nb], af[ma], bf[nb]);
        }

        bufw = (bufw == 2) ? 0 : bufw + 1;
        __syncthreads();
    }

    if (Ch) {
        #pragma unroll
        for (int ma = 0; ma < 2; ma++) {
            const int r0 = bm + wm*32 + ma*16 + g;
            #pragma unroll
            for (int nb = 0; nb < 8; nb++) {
                const int c0 = bn + wn*64 + nb*8 + 2*t;
                const float sc = (c0 < scale_cols) ? QSCALE : 1.0f;
                *(uint32_t*)&Ch[(size_t)r0     * N + c0] = pkh(acc[ma][nb][0]*sc, acc[ma][nb][1]*sc);
                *(uint32_t*)&Ch[(size_t)(r0+8) * N + c0] = pkh(acc[ma][nb][2]*sc, acc[ma][nb][3]*sc);
            }
        }
    } else {
        #pragma unroll
        for (int ma = 0; ma < 2; ma++) {
            const int r0 = bm + wm*32 + ma*16 + g;
            #pragma unroll
            for (int nb = 0; nb < 8; nb++) {
                const int c0 = bn + wn*64 + nb*8 + 2*t;
                *(float2*)&Cf[(size_t)r0     * N + c0] = make_float2(acc[ma][nb][0], acc[ma][nb][1]);
                *(float2*)&Cf[(size_t)(r0+8) * N + c0] = make_float2(acc[ma][nb][2], acc[ma][nb][3]);
            }
        }
    }
}

// ---------------------------------------------------------------------------
// Flash attention, fp16 in/out, double-buffered KV (1 sync/tile), exp2 softmax.
// ---------------------------------------------------------------------------
#define ARB 144                  // row stride bytes (72 fp16)
#define KVSTG (64*72*2)          // one KV stage in halves (K + V) = 18432 B

__global__ void __launch_bounds__(256) attn_h16(const __half* __restrict__ qkv,
                                                __half* __restrict__ outp)
{
    __shared__ __align__(16) __half sh[2*KVSTG];    // 36864 B (2 stages)
    __half* Qs = sh;                                // Q staging overlays stage 0

    const int tid = threadIdx.x;
    const int lane = tid & 31, wid = tid >> 5;
    const int g = lane >> 2, t = lane & 3;
    const int bh = blockIdx.y, b = bh >> 4, h = bh & 15;
    const int q0 = (gridDim.x - 1 - blockIdx.x) * 128;   // longest first
    const __half* base = qkv + (size_t)b * SEQ * QKVCOL;

    const uint32_t S0 = smem_u32(sh);
    const uint32_t a_lo = (uint32_t)((lane & 15) * ARB + (lane >> 4) * 16);
    const uint32_t b_lo = (uint32_t)(((lane & 7) + ((lane >> 4) & 1) * 8) * ARB + ((lane >> 3) & 1) * 16);
    const uint32_t v_lo = (uint32_t)(((lane & 7) + ((lane >> 3) & 1) * 8) * ARB + (lane >> 4) * 16);

    // stage Q (already scaled by QSCALE): plain copy
    {
        const int r = tid >> 1;
        const __half* qr = base + (size_t)(q0 + r) * QKVCOL + h*DH + (tid & 1) * 32;
        const uint32_t dst = S0 + (uint32_t)(r * ARB + (tid & 1) * 64);
        #pragma unroll
        for (int i = 0; i < 4; i++) {
            uint4 v = ((const uint4*)qr)[i];
            STS16(dst + i*16, v);
        }
    }
    __syncthreads();

    uint32_t qf[4][4];
    #pragma unroll
    for (int kc = 0; kc < 4; kc++)
        ldsm4(qf[kc][0], qf[kc][1], qf[kc][2], qf[kc][3],
              S0 + (uint32_t)(wid * 16 * ARB + kc * 32) + a_lo);
    __syncthreads();

    float o[8][4] = {};
    float m0 = -INFINITY, m1 = -INFINITY, l0 = 0.f, l1 = 0.f;
    const int row0 = q0 + wid*16 + g;
    const int ntiles = q0/64 + 2;

    // fill mapping: row tid&63, 16 fp16 (32B) at col offset (tid>>6)*16
    const int fr = tid & 63, fc = (tid >> 6) * 16;
    const __half* Kg = base + (size_t)fr * QKVCOL +     DIM + h*DH + fc;
    const __half* Vg = base + (size_t)fr * QKVCOL + 2 * DIM + h*DH + fc;
    const size_t tstep = (size_t)64 * QKVCOL;
    const uint32_t koff = (uint32_t)(fr * ARB + fc * 2);           // within stage
    const uint32_t voff = koff + (uint32_t)(64 * ARB);

    // prologue: tile 0 -> stage 0
    uint4 rk[2], rv[2];
    #pragma unroll
    for (int i = 0; i < 2; i++) { rk[i] = ((const uint4*)Kg)[i]; rv[i] = ((const uint4*)Vg)[i]; }
    #pragma unroll
    for (int i = 0; i < 2; i++) {
        STS16(S0 + koff + i*16, rk[i]);
        STS16(S0 + voff + i*16, rv[i]);
    }
    __syncthreads();

    for (int kt = 0; kt < ntiles; kt++) {
        // LDG next tile early (lands during compute)
        if (kt + 1 < ntiles) {
            const __half* Kg2 = Kg + (size_t)(kt + 1) * tstep;
            const __half* Vg2 = Vg + (size_t)(kt + 1) * tstep;
            #pragma unroll
            for (int i = 0; i < 2; i++) { rk[i] = ((const uint4*)Kg2)[i]; rv[i] = ((const uint4*)Vg2)[i]; }
        }

        const uint32_t Ks0 = S0 + (uint32_t)(kt & 1) * (KVSTG * 2);
        const uint32_t Vs0 = Ks0 + (uint32_t)(64 * ARB);

        // ---- S = Q @ K^T ----
        float s[8][4] = {};
        #pragma unroll
        for (int kc = 0; kc < 4; kc++) {
            uint32_t bk[8][2];
            #pragma unroll
            for (int p = 0; p < 4; p++)
                ldsm4(bk[2*p][0], bk[2*p][1], bk[2*p+1][0], bk[2*p+1][1],
                      Ks0 + (uint32_t)(p * 16 * ARB + kc * 32) + b_lo);
            #pragma unroll
            for (int nb = 0; nb < 8; nb++)
                mma16(s[nb], qf[kc], bk[nb]);
        }

        // ---- causal mask + online softmax (log2 domain) ----
        const int colbase = kt*64 + 2*t;
        float t0 = -INFINITY, t1 = -INFINITY;
        #pragma unroll
        for (int na = 0; na < 8; na++) {
            const int c = colbase + na*8;
            if (c     > row0)     s[na][0] = -INFINITY;
            if (c + 1 > row0)     s[na][1] = -INFINITY;
            if (c     > row0 + 8) s[na][2] = -INFINITY;
            if (c + 1 > row0 + 8) s[na][3] = -INFINITY;
            t0 = fmaxf(t0, fmaxf(s[na][0], s[na][1]));
            t1 = fmaxf(t1, fmaxf(s[na][2], s[na][3]));
        }
        t0 = fmaxf(t0, __shfl_xor_sync(0xffffffffu, t0, 1));
        t0 = fmaxf(t0, __shfl_xor_sync(0xffffffffu, t0, 2));
        t1 = fmaxf(t1, __shfl_xor_sync(0xffffffffu, t1, 1));
        t1 = fmaxf(t1, __shfl_xor_sync(0xffffffffu, t1, 2));

        const float mn0 = fmaxf(m0, t0), mn1 = fmaxf(m1, t1);
        const float sc0 = exp2f(m0 - mn0), sc1 = exp2f(m1 - mn1);
        m0 = mn0; m1 = mn1; l0 *= sc0; l1 *= sc1;

        #pragma unroll
        for (int na = 0; na < 8; na++) {
            o[na][0] *= sc0; o[na][1] *= sc0; o[na][2] *= sc1; o[na][3] *= sc1;
            s[na][0] = exp2f(s[na][0] - m0);
            s[na][1] = exp2f(s[na][1] - m0);
            s[na][2] = exp2f(s[na][2] - m1);
            s[na][3] = exp2f(s[na][3] - m1);
            l0 += s[na][0] + s[na][1];
            l1 += s[na][2] + s[na][3];
        }

        // ---- O += P @ V ----
        #pragma unroll
        for (int kc = 0; kc < 4; kc++) {
            uint32_t pa[4];
            pa[0] = pkh(s[2*kc][0],   s[2*kc][1]);
            pa[1] = pkh(s[2*kc][2],   s[2*kc][3]);
            pa[2] = pkh(s[2*kc+1][0], s[2*kc+1][1]);
            pa[3] = pkh(s[2*kc+1][2], s[2*kc+1][3]);

            uint32_t bv[8][2];
            #pragma unroll
            for (int p = 0; p < 4; p++)
                ldsm4t(bv[2*p][0], bv[2*p][1], bv[2*p+1][0], bv[2*p+1][1],
                       Vs0 + (uint32_t)(kc * 16 * ARB + p * 32) + v_lo);
            #pragma unroll
            for (int nb = 0; nb < 8; nb++)
                mma16(o[nb], pa, bv[nb]);
        }

        // STS next tile into the other stage (no reader until after sync)
        if (kt + 1 < ntiles) {
            const uint32_t D0 = S0 + (uint32_t)((kt + 1) & 1) * (KVSTG * 2);
            #pragma unroll
            for (int i = 0; i < 2; i++) {
                STS16(D0 + koff + i*16, rk[i]);
                STS16(D0 + voff + i*16, rv[i]);
            }
        }
        __syncthreads();
    }

    l0 += __shfl_xor_sync(0xffffffffu, l0, 1);
    l0 += __shfl_xor_sync(0xffffffffu, l0, 2);
    l1 += __shfl_xor_sync(0xffffffffu, l1, 1);
    l1 += __shfl_xor_sync(0xffffffffu, l1, 2);
    const float i0 = 1.f / l0, i1 = 1.f / l1;

    __half* orow0 = outp + (size_t)(b*SEQ + row0) * DIM + h*DH;
    __half* orow1 = orow0 + 8*DIM;
    #pragma unroll
    for (int na = 0; na < 8; na++) {
        *(uint32_t*)&orow0[na*8 + 2*t] = pkh(o[na][0]*i0, o[na][1]*i0);
        *(uint32_t*)&orow1[na*8 + 2*t] = pkh(o[na][2]*i1, o[na][3]*i1);
    }
}

// ---------------------------------------------------------------------------
extern "C" void kernel_launch(void* const* d_in, const int* in_sizes, int n_in,
                              void* d_out, int out_size)
{
    const float* x     = (const float*)d_in[0];
    const float* W_qkv = (const float*)d_in[1];
    const float* W_out = (const float*)d_in[2];
    float*       out   = (float*)d_out;

    __half *qkvh, *attnh, *xh, *wqh, *woh;
    cudaGetSymbolAddress((void**)&qkvh,  g_qkvh);
    cudaGetSymbolAddress((void**)&attnh, g_attnh);
    cudaGetSymbolAddress((void**)&xh,    g_xh);
    cudaGetSymbolAddress((void**)&wqh,   g_wqh);
    cudaGetSymbolAddress((void**)&woh,   g_woh);

    cudaFuncSetAttribute(gemm_h16, cudaFuncAttributeMaxDynamicSharedMemorySize, G_SMEM);

    // 0) convert all inputs to fp16 (single fused kernel)
    const int na8 = MROWS*DIM/8, nb8 = QKVCOL*DIM/8, nc8 = DIM*DIM/8;
    cvt3<<<(na8 + nb8 + nc8 + 255)/256, 256>>>(x, xh, na8, W_qkv, wqh, nb8, W_out, woh, nc8);

    // 1) qkv = x @ W_qkv^T (fp16 out; Q columns pre-scaled by QSCALE)
    gemm_h16<<<dim3(QKVCOL/128, MROWS/128), 256, G_SMEM>>>(xh, wqh, qkvh, nullptr,
                                                           MROWS, QKVCOL, DIM, DIM);
    // 2) causal attention (fp16 in/out)
    attn_h16<<<dim3(SEQ/128, BATCH*HEADS), 256>>>(qkvh, attnh);
    // 3) out = attn @ W_out^T (fp32 out)
    gemm_h16<<<dim3(DIM/128, MROWS/128), 256, G_SMEM>>>(attnh, woh, nullptr, out,
                                                        MROWS, DIM, DIM, 0);
}